// round 1
// baseline (speedup 1.0000x reference)
#include <cuda_runtime.h>

// ---------------------------------------------------------------------------
// RNN_70480413327462: 59-step patch-grid RNN + 9-neighbor center attention.
// Persistent kernel, 1 warp = 1 patch (both batch rows), 1 grid barrier/step.
// ---------------------------------------------------------------------------

#define NBLK   148
#define NTHR   896
#define NWARPS 28
#define PP     4096
#define NROWS  8192
#define HH     32
#define TSTEPS 59
#define NOBS   10
#define KPAD   36
#define INV_SQRT_E 0.1714985851425088f   // 1/sqrt(34)

// double-buffered Q/K/V scratch (step parity), padded rows of 36 floats
__device__ float g_Q[2][NROWS * KPAD];
__device__ float g_K[2][NROWS * KPAD];
__device__ float g_V[2][NROWS * KPAD];
__device__ unsigned g_arrive = 0;
__device__ volatile unsigned g_gen = 0;

__device__ __forceinline__ float warpAllSum(float v) {
#pragma unroll
    for (int o = 16; o > 0; o >>= 1) v += __shfl_xor_sync(0xffffffffu, v, o);
    return v;
}

__global__ void __launch_bounds__(NTHR, 1) rnn_kernel(
    const float* __restrict__ x,
    const float* __restrict__ W_x2h, const float* __restrict__ b_x2h,
    const float* __restrict__ W_h2h, const float* __restrict__ b_h2h,
    const float* __restrict__ W_fc2, const float* __restrict__ b_fc2,
    const float* __restrict__ ln_g,  const float* __restrict__ ln_b,
    const float* __restrict__ W_fcsa,const float* __restrict__ b_fcsa,
    const float* __restrict__ W_in,  const float* __restrict__ b_in,
    const float* __restrict__ W_out, const float* __restrict__ b_out,
    float* __restrict__ out)
{
    // --- shared weight tables (transposed for conflict-free column reads) ---
    __shared__ float2 A2[32][32];          // {W_x2h^T, W_h2h^T}[i][e]
    __shared__ float4 Wqkv4[32][34];       // {Wq^T, Wk^T, Wv^T, 0}[i][e]
    __shared__ float4 c0w4[34], c1w4[34], bqkv4[34];  // coord cols + bias per e
    __shared__ float  Wext[6][32];         // extra-output rows (e=32,33 of q,k,v)
    __shared__ float  ec0s[6], ec1s[6], ebs[6];
    __shared__ float  MT[34][32];          // (W_fcsa @ W_out)^T  [f][e]
    __shared__ float  bbs[32];             // b_out@W_fcsa^T + b_fcsa
    __shared__ float  Wfc2T[32][32];
    __shared__ float  bfc2s[32], lngs[32], lnbs[32], bcombs[32];
    __shared__ unsigned s_base;

    const int tid = threadIdx.x;

    // ---------------- smem init ----------------
    for (int idx = tid; idx < 32 * 32; idx += NTHR) {
        int i = idx >> 5, e = idx & 31;
        A2[i][e]    = make_float2(W_x2h[e * 32 + i], W_h2h[e * 32 + i]);
        Wfc2T[i][e] = W_fc2[e * 32 + i];
    }
    for (int idx = tid; idx < 32 * 34; idx += NTHR) {
        int i = idx & 31, e = idx >> 5;   // e in 0..33
        Wqkv4[i][e] = make_float4(W_in[e * 34 + i],
                                  W_in[(34 + e) * 34 + i],
                                  W_in[(68 + e) * 34 + i], 0.f);
    }
    if (tid < 34) {
        int e = tid;
        c0w4[e]  = make_float4(W_in[e*34+32], W_in[(34+e)*34+32], W_in[(68+e)*34+32], 0.f);
        c1w4[e]  = make_float4(W_in[e*34+33], W_in[(34+e)*34+33], W_in[(68+e)*34+33], 0.f);
        bqkv4[e] = make_float4(b_in[e], b_in[34+e], b_in[68+e], 0.f);
    }
    for (int idx = tid; idx < 6 * 32; idx += NTHR) {
        int j = idx >> 5, i = idx & 31;
        int row = (j >> 1) * 34 + 32 + (j & 1);
        Wext[j][i] = W_in[row * 34 + i];
    }
    if (tid < 6) {
        int row = (tid >> 1) * 34 + 32 + (tid & 1);
        ec0s[tid] = W_in[row * 34 + 32];
        ec1s[tid] = W_in[row * 34 + 33];
        ebs[tid]  = b_in[row];
    }
    for (int idx = tid; idx < 34 * 32; idx += NTHR) {
        int f = idx >> 5, e = idx & 31;
        float acc = 0.f;
        for (int g = 0; g < 34; g++) acc += W_fcsa[e * 34 + g] * W_out[g * 34 + f];
        MT[f][e] = acc;
    }
    if (tid < 32) {
        float acc = b_fcsa[tid];
        for (int g = 0; g < 34; g++) acc += b_out[g] * W_fcsa[tid * 34 + g];
        bbs[tid]   = acc;
        bfc2s[tid] = b_fc2[tid];
        lngs[tid]  = ln_g[tid];
        lnbs[tid]  = ln_b[tid];
        bcombs[tid]= b_x2h[tid] + b_h2h[tid];
    }
    if (tid == 0) s_base = g_gen;   // safe: no barrier can complete before we arrive
    __syncthreads();

    const unsigned sbase = s_base;
    const int lane = tid & 31;
    const int wid  = tid >> 5;
    const int p    = blockIdx.x * NWARPS + wid;
    const bool active = (p < PP);

    // per-patch constants
    int nb0[9];
    int pq = 0;
    float bql = 0.f, bkl = 0.f, bvl = 0.f;
    float exc[6] = {0,0,0,0,0,0};
    if (active) {
        int r = p >> 6, cI = p & 63;
        float c0 = (float)r  * (1.f / 64.f);
        float c1 = (float)cI * (1.f / 64.f);
        int rc  = min(max(r, 1), 62);
        int ccn = min(max(cI, 1), 62);
        pq = rc * 64 + ccn;                       // center-query patch (boundary shift)
#pragma unroll
        for (int m = 0; m < 9; m++)
            nb0[m] = (rc + m / 3 - 1) * 64 + (ccn + m % 3 - 1);
        {
            float4 a = bqkv4[lane], bw = c0w4[lane], cw = c1w4[lane];
            bql = a.x + c0 * bw.x + c1 * cw.x;
            bkl = a.y + c0 * bw.y + c1 * cw.y;
            bvl = a.z + c0 * bw.z + c1 * cw.z;
        }
#pragma unroll
        for (int j = 0; j < 6; j++) exc[j] = ebs[j] + c0 * ec0s[j] + c1 * ec1s[j];
    }

    float h0 = 0.f, h1 = 0.f, pred0 = 0.f, pred1 = 0.f;
    float ht0 = 0.f, ht1 = 0.f;

    for (int t = 0; t < TSTEPS; t++) {
        const int buf = t & 1;
        float* Qb = g_Q[buf];
        float* Kb = g_K[buf];
        float* Vb = g_V[buf];

        // =============== PHASE 1: RNN cell + QKV produce ===============
        if (active) {
            float inp0, inp1;
            if (t < NOBS) {
                inp0 = x[((size_t)t * NROWS + p) * HH + lane];
                inp1 = x[((size_t)t * NROWS + PP + p) * HH + lane];
            } else { inp0 = pred0; inp1 = pred1; }

            float a0 = bcombs[lane];
            float a1 = a0;
#pragma unroll
            for (int i = 0; i < 32; i++) {
                float2 w = A2[i][lane];
                a0 = fmaf(__shfl_sync(0xffffffffu, inp0, i), w.x, a0);
                a0 = fmaf(__shfl_sync(0xffffffffu, h0,   i), w.y, a0);
                a1 = fmaf(__shfl_sync(0xffffffffu, inp1, i), w.x, a1);
                a1 = fmaf(__shfl_sync(0xffffffffu, h1,   i), w.y, a1);
            }
            ht0 = tanhf(a0);
            ht1 = tanhf(a1);

            float q0 = bql, k0 = bkl, v0 = bvl;
            float q1 = bql, k1 = bkl, v1 = bvl;
#pragma unroll
            for (int i = 0; i < 32; i++) {
                float4 w = Wqkv4[i][lane];
                float hi0 = __shfl_sync(0xffffffffu, ht0, i);
                float hi1 = __shfl_sync(0xffffffffu, ht1, i);
                q0 = fmaf(hi0, w.x, q0); k0 = fmaf(hi0, w.y, k0); v0 = fmaf(hi0, w.z, v0);
                q1 = fmaf(hi1, w.x, q1); k1 = fmaf(hi1, w.y, k1); v1 = fmaf(hi1, w.z, v1);
            }
            // elements 32,33 of q/k/v via warp reductions
            float ex0[6], ex1[6];
#pragma unroll
            for (int j = 0; j < 6; j++) {
                float wv = Wext[j][lane];
                ex0[j] = warpAllSum(ht0 * wv) + exc[j];
                ex1[j] = warpAllSum(ht1 * wv) + exc[j];
            }
            size_t r0 = (size_t)p * KPAD, r1 = (size_t)(PP + p) * KPAD;
            Qb[r0 + lane] = q0; Kb[r0 + lane] = k0; Vb[r0 + lane] = v0;
            Qb[r1 + lane] = q1; Kb[r1 + lane] = k1; Vb[r1 + lane] = v1;
            if (lane < 2) {
                Qb[r0 + 32 + lane] = lane ? ex0[1] : ex0[0];
                Kb[r0 + 32 + lane] = lane ? ex0[3] : ex0[2];
                Vb[r0 + 32 + lane] = lane ? ex0[5] : ex0[4];
                Qb[r1 + 32 + lane] = lane ? ex1[1] : ex1[0];
                Kb[r1 + 32 + lane] = lane ? ex1[3] : ex1[2];
                Vb[r1 + 32 + lane] = lane ? ex1[5] : ex1[4];
            }
        }

        // =============== GRID BARRIER (one per step) ===============
        {
            __threadfence();
            __syncthreads();
            if (tid == 0) {
                unsigned want = sbase + (unsigned)t + 1u;
                unsigned tk = atomicAdd(&g_arrive, 1u);
                if ((tk % (unsigned)NBLK) == (unsigned)(NBLK - 1)) {
                    g_gen = want;                    // single releaser
                } else {
                    while ((int)(g_gen - want) < 0) __nanosleep(64);
                }
            }
            __syncthreads();
            __threadfence();
        }

        // =============== PHASE 2: attention gather + update + pred ===============
        if (active) {
            float o0 = 0.f, o1 = 0.f, ox0 = 0.f, ox1 = 0.f;
#pragma unroll
            for (int brow = 0; brow < 2; brow++) {
                const size_t boff = brow ? (size_t)PP * KPAD : 0;
                const float* qp = Qb + boff + (size_t)pq * KPAD;
                float q  = __ldcg(qp + lane);
                float qx = 0.f;
                if (lane < 2) qx = __ldcg(qp + 32 + lane);
                float s[9];
#pragma unroll
                for (int m = 0; m < 9; m++) {
                    const float* kp = Kb + boff + (size_t)nb0[m] * KPAD;
                    float part = q * __ldcg(kp + lane);
                    if (lane < 2) part += qx * __ldcg(kp + 32 + lane);
                    s[m] = warpAllSum(part);
                }
                float mx = s[0];
#pragma unroll
                for (int m = 1; m < 9; m++) mx = fmaxf(mx, s[m]);
                float sum = 0.f;
#pragma unroll
                for (int m = 0; m < 9; m++) {
                    s[m] = __expf((s[m] - mx) * INV_SQRT_E);
                    sum += s[m];
                }
                float inv = __fdividef(1.f, sum);
                float oa = 0.f, oxa = 0.f;
#pragma unroll
                for (int m = 0; m < 9; m++) {
                    const float* vp = Vb + boff + (size_t)nb0[m] * KPAD;
                    float w = s[m] * inv;
                    oa = fmaf(w, __ldcg(vp + lane), oa);
                    if (lane < 2) oxa = fmaf(w, __ldcg(vp + 32 + lane), oxa);
                }
                if (brow == 0) { o0 = oa; ox0 = oxa; } else { o1 = oa; ox1 = oxa; }
            }

            // fused out-proj + fcsa:  h += o @ M^T + bb
            float d0 = bbs[lane], d1 = bbs[lane];
#pragma unroll
            for (int f = 0; f < 32; f++) {
                float w = MT[f][lane];
                d0 = fmaf(__shfl_sync(0xffffffffu, o0, f), w, d0);
                d1 = fmaf(__shfl_sync(0xffffffffu, o1, f), w, d1);
            }
            {
                float w32 = MT[32][lane], w33 = MT[33][lane];
                float e0a = __shfl_sync(0xffffffffu, ox0, 0);
                float e0b = __shfl_sync(0xffffffffu, ox0, 1);
                d0 = fmaf(e0a, w32, fmaf(e0b, w33, d0));
                float e1a = __shfl_sync(0xffffffffu, ox1, 0);
                float e1b = __shfl_sync(0xffffffffu, ox1, 1);
                d1 = fmaf(e1a, w32, fmaf(e1b, w33, d1));
            }
            h0 = ht0 + d0;
            h1 = ht1 + d1;

            // fc2 + layernorm -> pred
            float y0 = bfc2s[lane], y1 = bfc2s[lane];
#pragma unroll
            for (int i = 0; i < 32; i++) {
                float w = Wfc2T[i][lane];
                y0 = fmaf(__shfl_sync(0xffffffffu, h0, i), w, y0);
                y1 = fmaf(__shfl_sync(0xffffffffu, h1, i), w, y1);
            }
            float m0 = warpAllSum(y0) * (1.f / 32.f);
            float dd0 = y0 - m0;
            float var0 = warpAllSum(dd0 * dd0) * (1.f / 32.f);
            pred0 = dd0 * rsqrtf(var0 + 1e-5f) * lngs[lane] + lnbs[lane];
            float m1 = warpAllSum(y1) * (1.f / 32.f);
            float dd1 = y1 - m1;
            float var1 = warpAllSum(dd1 * dd1) * (1.f / 32.f);
            pred1 = dd1 * rsqrtf(var1 + 1e-5f) * lngs[lane] + lnbs[lane];

            out[((size_t)t * NROWS + p) * HH + lane]      = pred0;
            out[((size_t)t * NROWS + PP + p) * HH + lane] = pred1;
        }
    }
}

extern "C" void kernel_launch(void* const* d_in, const int* in_sizes, int n_in,
                              void* d_out, int out_size) {
    (void)in_sizes; (void)n_in; (void)out_size;
    rnn_kernel<<<NBLK, NTHR>>>(
        (const float*)d_in[0],
        (const float*)d_in[1],  (const float*)d_in[2],
        (const float*)d_in[3],  (const float*)d_in[4],
        (const float*)d_in[5],  (const float*)d_in[6],
        (const float*)d_in[7],  (const float*)d_in[8],
        (const float*)d_in[9],  (const float*)d_in[10],
        (const float*)d_in[11], (const float*)d_in[12],
        (const float*)d_in[13], (const float*)d_in[14],
        (float*)d_out);
}

// round 2
// speedup vs baseline: 1.2934x; 1.2934x over previous
#include <cuda_runtime.h>

// ---------------------------------------------------------------------------
// RNN_70480413327462: 59-step patch-grid RNN + 9-neighbor center attention.
// Persistent kernel, 1 warp = 1 patch (both batch rows), 1 grid barrier/step.
// R2: smem-staged LDS.128 GEMVs; per-lane attention dots; fast tanh.
// ---------------------------------------------------------------------------

#define NBLK   148
#define NTHR   896
#define NWARPS 28
#define PP     4096
#define NROWS  8192
#define HH     32
#define TSTEPS 59
#define NOBS   10
#define KPAD   36
#define INV_SQRT_E 0.1714985851425088f   // 1/sqrt(34)

// double-buffered Q/K/V scratch (step parity), padded rows of 36 floats
__device__ float g_Q[2][NROWS * KPAD];
__device__ float g_K[2][NROWS * KPAD];
__device__ float g_V[2][NROWS * KPAD];
__device__ unsigned g_arrive = 0;
__device__ volatile unsigned g_gen = 0;

struct Smem {
    float4 Wc[32][17];        // RNN merged: c<8 -> W_x2h chunk, c>=8 -> W_h2h chunk (pad 17)
    float4 Wq[32][9];         // W_in q rows, i-chunks (8 used, pad 9)
    float4 Wk[32][9];
    float4 Wv[32][9];
    float4 Mw[32][9];         // (W_fcsa@W_out)^T packed over f-chunks (9 used)
    float4 Wf[32][9];         // W_fc2 chunks (8 used)
    float4 We[6][9];          // ext rows (q32,q33,k32,k33,v32,v33) chunks (8 used)
    float4 RB[NWARPS][2][17]; // per-warp stage: [0..7] inp/ht/o, [8]=o8, [9..16]=h
    int    NBS[NWARPS][12];   // 9 neighbor row-offsets (elements)
    unsigned sbase;
};

__device__ __forceinline__ float warpAllSum(float v) {
#pragma unroll
    for (int o = 16; o > 0; o >>= 1) v += __shfl_xor_sync(0xffffffffu, v, o);
    return v;
}

__device__ __forceinline__ float ftanh(float x) {
    float e = __expf(2.f * x);
    return 1.f - __fdividef(2.f, e + 1.f);
}

__device__ __forceinline__ float dot4(float4 a, float4 b) {
    return fmaf(a.x, b.x, fmaf(a.y, b.y, fmaf(a.z, b.z, a.w * b.w)));
}

extern __shared__ unsigned char smem_raw[];

__global__ void __launch_bounds__(NTHR, 1) rnn_kernel(
    const float* __restrict__ x,
    const float* __restrict__ W_x2h, const float* __restrict__ b_x2h,
    const float* __restrict__ W_h2h, const float* __restrict__ b_h2h,
    const float* __restrict__ W_fc2, const float* __restrict__ b_fc2,
    const float* __restrict__ ln_g,  const float* __restrict__ ln_b,
    const float* __restrict__ W_fcsa,const float* __restrict__ b_fcsa,
    const float* __restrict__ W_in,  const float* __restrict__ b_in,
    const float* __restrict__ W_out, const float* __restrict__ b_out,
    float* __restrict__ out)
{
    Smem* sm = reinterpret_cast<Smem*>(smem_raw);
    const int tid = threadIdx.x;

    // ---------------- smem weight init ----------------
    for (int idx = tid; idx < 32 * 16; idx += NTHR) {
        int e = idx >> 4, c = idx & 15;
        const float* src = (c < 8) ? (W_x2h + e * 32 + c * 4)
                                   : (W_h2h + e * 32 + (c - 8) * 4);
        sm->Wc[e][c] = make_float4(src[0], src[1], src[2], src[3]);
    }
    for (int idx = tid; idx < 32 * 8; idx += NTHR) {
        int e = idx >> 3, c = idx & 7, i = c * 4;
        const float* q = W_in + e * 34 + i;
        const float* k = W_in + (34 + e) * 34 + i;
        const float* v = W_in + (68 + e) * 34 + i;
        const float* f = W_fc2 + e * 32 + i;
        sm->Wq[e][c] = make_float4(q[0], q[1], q[2], q[3]);
        sm->Wk[e][c] = make_float4(k[0], k[1], k[2], k[3]);
        sm->Wv[e][c] = make_float4(v[0], v[1], v[2], v[3]);
        sm->Wf[e][c] = make_float4(f[0], f[1], f[2], f[3]);
    }
    for (int idx = tid; idx < 32 * 9; idx += NTHR) {
        int e = idx / 9, c = idx % 9;
        float w[4];
#pragma unroll
        for (int d = 0; d < 4; d++) {
            int f = c * 4 + d;
            float acc = 0.f;
            if (f < 34)
                for (int g = 0; g < 34; g++)
                    acc += W_fcsa[e * 34 + g] * W_out[g * 34 + f];
            w[d] = acc;
        }
        sm->Mw[e][c] = make_float4(w[0], w[1], w[2], w[3]);
    }
    for (int idx = tid; idx < 6 * 8; idx += NTHR) {
        int j = idx >> 3, c = idx & 7;
        int row = (j >> 1) * 34 + 32 + (j & 1);
        const float* src = W_in + row * 34 + c * 4;
        sm->We[j][c] = make_float4(src[0], src[1], src[2], src[3]);
    }
    if (tid == 0) sm->sbase = g_gen;

    const int lane = tid & 31;
    const int wid  = tid >> 5;
    const int p    = blockIdx.x * NWARPS + wid;
    const bool active = (p < PP);

    // ---------------- per-lane constants ----------------
    int pqOff = 0;
    float bql = 0.f, bkl = 0.f, bvl = 0.f;
    float bcombL = 0.f, bfL = 0.f, lngL = 0.f, lnbL = 0.f, bbL = 0.f;
    float exC = 0.f;
    int   eoff = 0;
    const int sRow = lane >> 4;           // attention half: 0->batch0, 1->batch1
    const int sM   = lane & 15;           // per-half index
    const bool sAct = (sM < 9);
    const bool eAct = (sM < 6);

    if (active) {
        int r = p >> 6, cI = p & 63;
        float c0 = (float)r  * (1.f / 64.f);
        float c1 = (float)cI * (1.f / 64.f);
        int rc  = min(max(r, 1), 62);
        int ccn = min(max(cI, 1), 62);
        pqOff = (rc * 64 + ccn) * KPAD;
        if (lane < 9)
            sm->NBS[wid][lane] = ((rc + lane / 3 - 1) * 64 + (ccn + lane % 3 - 1)) * KPAD;

        bql = b_in[lane]      + c0 * W_in[lane * 34 + 32]      + c1 * W_in[lane * 34 + 33];
        bkl = b_in[34 + lane] + c0 * W_in[(34 + lane) * 34 + 32] + c1 * W_in[(34 + lane) * 34 + 33];
        bvl = b_in[68 + lane] + c0 * W_in[(68 + lane) * 34 + 32] + c1 * W_in[(68 + lane) * 34 + 33];
        bcombL = b_x2h[lane] + b_h2h[lane];
        bfL  = b_fc2[lane];
        lngL = ln_g[lane];
        lnbL = ln_b[lane];
        {
            float acc = b_fcsa[lane];
            for (int g = 0; g < 34; g++) acc += b_out[g] * W_fcsa[lane * 34 + g];
            bbL = acc;
        }
        if (eAct) {
            int j = sM;
            int row = (j >> 1) * 34 + 32 + (j & 1);
            exC = b_in[row] + c0 * W_in[row * 34 + 32] + c1 * W_in[row * 34 + 33];
            eoff = ((sRow ? PP + p : p)) * KPAD + 32 + (j & 1);
        }
        // zero h staging + QKV row pads (elements 34,35) once
        ((float*)sm->RB[wid][0])[36 + lane] = 0.f;
        ((float*)sm->RB[wid][1])[36 + lane] = 0.f;
        if (lane < 2) {
#pragma unroll
            for (int par = 0; par < 2; par++) {
#pragma unroll
                for (int row = 0; row < 2; row++) {
                    size_t o = (size_t)(row * PP + p) * KPAD + 34 + lane;
                    g_Q[par][o] = 0.f; g_K[par][o] = 0.f; g_V[par][o] = 0.f;
                }
            }
        }
    }
    __syncthreads();

    const unsigned sbase = sm->sbase;
    int nbBase = (active && sAct) ? sm->NBS[wid][sM] : 0;
    const int rowAdd = sRow * PP * KPAD;
    const int kOffR  = nbBase + rowAdd;
    const int qOffR  = pqOff + rowAdd;
    const int r0Off  = p * KPAD + lane;
    const int r1Off  = (PP + p) * KPAD + lane;

    float4* RB0 = sm->RB[wid][0];
    float4* RB1 = sm->RB[wid][1];
    float*  RB0f = (float*)RB0;
    float*  RB1f = (float*)RB1;

    float h0 = 0.f, h1 = 0.f, ht0 = 0.f, ht1 = 0.f;

    for (int t = 0; t < TSTEPS; t++) {
        const int buf = t & 1;
        float* Qb = g_Q[buf];
        float* Kb = g_K[buf];
        float* Vb = g_V[buf];

        // =============== PHASE 1: RNN cell + QKV produce ===============
        if (active) {
            if (t < NOBS) {   // stage external input (else pred already staged)
                RB0f[lane] = x[((size_t)t * NROWS + p) * HH + lane];
                RB1f[lane] = x[((size_t)t * NROWS + PP + p) * HH + lane];
            }
            __syncwarp();

            float a0 = bcombL, a1 = bcombL;
#pragma unroll
            for (int c = 0; c < 16; c++) {
                float4 w  = sm->Wc[lane][c];
                int dc = (c < 8) ? c : c + 1;     // h lives at chunks 9..16
                float4 u0 = RB0[dc];
                float4 u1 = RB1[dc];
                a0 += dot4(u0, w);
                a1 += dot4(u1, w);
            }
            ht0 = ftanh(a0);
            ht1 = ftanh(a1);

            __syncwarp();
            RB0f[lane] = ht0;    // stage ht in chunks 0..7 (overwrites inp)
            RB1f[lane] = ht1;
            __syncwarp();

            float q0 = bql, k0 = bkl, v0 = bvl;
            float q1 = bql, k1 = bkl, v1 = bvl;
#pragma unroll
            for (int c = 0; c < 8; c++) {
                float4 wq = sm->Wq[lane][c];
                float4 wk = sm->Wk[lane][c];
                float4 wv = sm->Wv[lane][c];
                float4 t0 = RB0[c];
                float4 t1 = RB1[c];
                q0 += dot4(t0, wq); k0 += dot4(t0, wk); v0 += dot4(t0, wv);
                q1 += dot4(t1, wq); k1 += dot4(t1, wk); v1 += dot4(t1, wv);
            }
            Qb[r0Off] = q0; Kb[r0Off] = k0; Vb[r0Off] = v0;
            Qb[r1Off] = q1; Kb[r1Off] = k1; Vb[r1Off] = v1;

            // extra elements e=32,33 of q/k/v: lanes 0-5 row0, 16-21 row1
            if (eAct) {
                const float4* htp = sRow ? RB1 : RB0;
                float ex = exC;
#pragma unroll
                for (int c = 0; c < 8; c++)
                    ex += dot4(htp[c], sm->We[sM][c]);
                float* eb = (sM < 2) ? Qb : ((sM < 4) ? Kb : Vb);
                eb[eoff] = ex;
            }
        }

        // =============== GRID BARRIER (one per step) ===============
        {
            __threadfence();
            __syncthreads();
            if (tid == 0) {
                unsigned want = sbase + (unsigned)t + 1u;
                unsigned tk = atomicAdd(&g_arrive, 1u);
                if ((tk % (unsigned)NBLK) == (unsigned)(NBLK - 1)) {
                    g_gen = want;                    // single releaser
                } else {
                    while ((int)(g_gen - want) < 0) __nanosleep(32);
                }
            }
            __syncthreads();
            __threadfence();
        }

        // =============== PHASE 2: attention + update + pred ===============
        if (active) {
            // --- scores: lane m of each half computes q . k_nb[m] over 36 ---
            float sc = -3.4e38f;
            if (sAct) {
                const float4* qrow = (const float4*)(Qb + qOffR);
                const float4* krow = (const float4*)(Kb + kOffR);
                float d = 0.f;
#pragma unroll
                for (int c = 0; c < 9; c++) {
                    float4 qc = __ldcg(qrow + c);
                    float4 kc = __ldcg(krow + c);
                    d += dot4(qc, kc);
                }
                sc = d;
            }
            // group softmax over 9 within each 16-lane half
            float mx = sc;
#pragma unroll
            for (int o = 8; o > 0; o >>= 1)
                mx = fmaxf(mx, __shfl_xor_sync(0xffffffffu, mx, o, 16));
            float ew = __expf((sc - mx) * INV_SQRT_E);
            float ssum = ew;
#pragma unroll
            for (int o = 8; o > 0; o >>= 1)
                ssum += __shfl_xor_sync(0xffffffffu, ssum, o, 16);
            float wgt = ew * __fdividef(1.f, ssum);

            // --- V mix: lane c of each half accumulates o-chunk c ---
            float4 o4 = make_float4(0.f, 0.f, 0.f, 0.f);
#pragma unroll
            for (int m = 0; m < 9; m++) {
                float wm = __shfl_sync(0xffffffffu, wgt, m, 16);
                int   nm = __shfl_sync(0xffffffffu, nbBase, m, 16);
                if (sAct) {
                    float4 vv = __ldcg((const float4*)(Vb + nm + rowAdd) + sM);
                    o4.x = fmaf(wm, vv.x, o4.x);
                    o4.y = fmaf(wm, vv.y, o4.y);
                    o4.z = fmaf(wm, vv.z, o4.z);
                    o4.w = fmaf(wm, vv.w, o4.w);
                }
            }
            if (sAct) (sRow ? RB1 : RB0)[sM] = o4;   // o chunks 0..8
            __syncwarp();

            // --- fused out-proj + fcsa: h = ht + o @ M^T + bb ---
            float d0 = bbL, d1 = bbL;
#pragma unroll
            for (int c = 0; c < 9; c++) {
                float4 wt = sm->Mw[lane][c];
                d0 += dot4(RB0[c], wt);
                d1 += dot4(RB1[c], wt);
            }
            h0 = ht0 + d0;
            h1 = ht1 + d1;

            // stage h (chunks 9..16) for fc2 + next-step RNN
            RB0f[36 + lane] = h0;
            RB1f[36 + lane] = h1;
            __syncwarp();

            // --- fc2 + layernorm -> pred ---
            float y0 = bfL, y1 = bfL;
#pragma unroll
            for (int c = 0; c < 8; c++) {
                float4 wt = sm->Wf[lane][c];
                y0 += dot4(RB0[9 + c], wt);
                y1 += dot4(RB1[9 + c], wt);
            }
            float m0 = warpAllSum(y0) * (1.f / 32.f);
            float dd0 = y0 - m0;
            float var0 = warpAllSum(dd0 * dd0) * (1.f / 32.f);
            float pred0 = dd0 * rsqrtf(var0 + 1e-5f) * lngL + lnbL;
            float m1 = warpAllSum(y1) * (1.f / 32.f);
            float dd1 = y1 - m1;
            float var1 = warpAllSum(dd1 * dd1) * (1.f / 32.f);
            float pred1 = dd1 * rsqrtf(var1 + 1e-5f) * lngL + lnbL;

            // stage pred as next-step input (chunks 0..7)
            RB0f[lane] = pred0;
            RB1f[lane] = pred1;

            out[((size_t)t * NROWS + p) * HH + lane]      = pred0;
            out[((size_t)t * NROWS + PP + p) * HH + lane] = pred1;
        }
    }
}

extern "C" void kernel_launch(void* const* d_in, const int* in_sizes, int n_in,
                              void* d_out, int out_size) {
    (void)in_sizes; (void)n_in; (void)out_size;
    cudaFuncSetAttribute(rnn_kernel, cudaFuncAttributeMaxDynamicSharedMemorySize,
                         (int)sizeof(Smem));
    rnn_kernel<<<NBLK, NTHR, sizeof(Smem)>>>(
        (const float*)d_in[0],
        (const float*)d_in[1],  (const float*)d_in[2],
        (const float*)d_in[3],  (const float*)d_in[4],
        (const float*)d_in[5],  (const float*)d_in[6],
        (const float*)d_in[7],  (const float*)d_in[8],
        (const float*)d_in[9],  (const float*)d_in[10],
        (const float*)d_in[11], (const float*)d_in[12],
        (const float*)d_in[13], (const float*)d_in[14],
        (float*)d_out);
}